// round 12
// baseline (speedup 1.0000x reference)
#include <cuda_runtime.h>

// Pool_26517128085982: 2x2 mean pool, stride 2, x:(16,64,512,512) f32 -> (16,64,256,256) f32
// Converged HBM-streaming kernel (~7.25 TB/s, 90.6% of spec; compulsory 1.342 GB traffic;
// band 186.5-187.0us across 7 structural variants, R6/R11 best at 186.5us).
// R12 — last untested mechanism: 256-bit vectorized global accesses (Blackwell
// ld/st.global.v8.f32). Each thread: 1 float8 output <- 4 float8 input loads
// (2 per source row). Warp-level transactions: 1KB per load instruction, fully
// contiguous. If ptxas legalizes v8 to 2x128-bit this degenerates to the proven
// R6 machine code (neutral); if native, fewer/larger requests at the L2/DRAM
// interface where the residual ~9% inefficiency lives.
// Flat one-shot grid, 256 thr/block, default cache policy (all proven best).

static constexpr int W_IN   = 512;
static constexpr int H_OUT  = 256;
static constexpr int ROW8_IN  = W_IN / 8;            // 64 float8 per input row
static constexpr int ROW8_OUT = 256 / 8;             // 32 float8 per output row
static constexpr int IMG8_IN  = W_IN * W_IN / 8;     // 32768 float8 per input image

struct f8 { float v[8]; };

__device__ __forceinline__ void ldg256(const float* __restrict__ p, f8& r)
{
    asm("ld.global.v8.f32 {%0,%1,%2,%3,%4,%5,%6,%7}, [%8];"
        : "=f"(r.v[0]), "=f"(r.v[1]), "=f"(r.v[2]), "=f"(r.v[3]),
          "=f"(r.v[4]), "=f"(r.v[5]), "=f"(r.v[6]), "=f"(r.v[7])
        : "l"(p));
}

__device__ __forceinline__ void stg256(float* __restrict__ p, const f8& r)
{
    asm volatile("st.global.v8.f32 [%0], {%1,%2,%3,%4,%5,%6,%7,%8};"
        :: "l"(p),
           "f"(r.v[0]), "f"(r.v[1]), "f"(r.v[2]), "f"(r.v[3]),
           "f"(r.v[4]), "f"(r.v[5]), "f"(r.v[6]), "f"(r.v[7])
        : "memory");
}

__global__ __launch_bounds__(256) void Pool_26517128085982_kernel(
    const float* __restrict__ in,
    const float* __restrict__ kern,    // 4 floats: k00 k01 k10 k11
    float* __restrict__ out,
    int n_out8)                        // out_size / 8
{
    int idx = blockIdx.x * blockDim.x + threadIdx.x;
    if (idx >= n_out8) return;

    // idx -> (img, oh, oc8): 32 float8 per out row, 256 rows per image
    int oc8 = idx & (ROW8_OUT - 1);          // 0..31
    int oh  = (idx >> 5) & (H_OUT - 1);      // 0..255
    int img = idx >> 13;                     // 0..1023

    // input base in float units: row 2*oh, col 16*oc8
    long base = (long)img * (IMG8_IN * 8) + (long)(oh << 1) * W_IN + (oc8 << 4);

    // 4 independent 256-bit loads (2 per source row), front-batched
    f8 a0, a1, b0, b1;
    ldg256(in + base,                a0);
    ldg256(in + base + 8,            a1);
    ldg256(in + base + W_IN,         b0);
    ldg256(in + base + W_IN + 8,     b1);

    // kernel weights: broadcast load, L1-hit after first warp
    float4 k = *reinterpret_cast<const float4*>(kern);

    f8 o;
    #pragma unroll
    for (int j = 0; j < 4; j++) {
        o.v[j]     = k.x * a0.v[2*j] + k.y * a0.v[2*j+1] + k.z * b0.v[2*j] + k.w * b0.v[2*j+1];
        o.v[j + 4] = k.x * a1.v[2*j] + k.y * a1.v[2*j+1] + k.z * b1.v[2*j] + k.w * b1.v[2*j+1];
    }

    stg256(out + (long)idx * 8, o);
}

extern "C" void kernel_launch(void* const* d_in, const int* in_sizes, int n_in,
                              void* d_out, int out_size)
{
    const float* x    = (const float*)d_in[0];
    const float* kern = (const float*)d_in[1];
    float*       out  = (float*)d_out;

    int n_out8 = out_size / 8;           // 8,388,608 float8
    int blocks = (n_out8 + 255) / 256;   // 32,768 blocks
    Pool_26517128085982_kernel<<<blocks, 256>>>(x, kern, out, n_out8);
}

// round 13
// speedup vs baseline: 1.0010x; 1.0010x over previous
#include <cuda_runtime.h>

// Pool_26517128085982: 2x2 mean pool, stride 2, x:(16,64,512,512) f32 -> (16,64,256,256) f32
// FINAL — converged at the DRAM roofline. Compulsory traffic 1.342 GB (1.074 GB read +
// 0.268 GB write, zero reuse, footprint >> L2) at ~7.25 TB/s achieved = 90.6% of 8 TB/s
// spec; residual ~9% is DRAM R/W turnaround + refresh, unreachable from SASS.
// Exploration (8 variants, all axes closed):
//   R3  flat MLP=4 default:         186.59us, DRAM 91.2%
//   R5  flat MLP=8 .cs load+store:  186.75us, DRAM 89.6%  (.cs loads hurt L2->DRAM sched)
//   R6  flat MLP=8 default:         186.56us, DRAM 91.5%  <== THIS KERNEL
//   R7  persistent grid-stride:     198.75us, DRAM 85.9%  (loop bubbles starve LDG stream)
//   R8  flat MLP=8 .cg loads:       186.88us, DRAM 91.4%  (L1 bypass neutral)
//   R9  flat MLP=8 block=512:       186.62us, DRAM 90.8%  (neutral)
//   R10 flat MLP=8 .cs stores:      186.94us, DRAM 91.0%  (neutral)
//   R11 re-bench of R6:             186.50us, DRAM 91.0%  (best timed)
//   R12 256-bit v8.f32 accesses:    187.07us, DRAM 91.4%  (neutral; occ 61% suffices)
// Design: flat one-shot grid (hardware distributor keeps the LDG stream dense — persistent
// loops demonstrably starve it), 256 thr/block, each thread produces 2 float4 outputs at
// idx and idx+n/2 so every warp-level transaction is fully contiguous, 8 front-batched
// LDG.128 (MLP=8), default cache policy both streams, generic 2x2 weights from d_in[1].

static constexpr int W_IN    = 512;
static constexpr int W_OUT   = 256;
static constexpr int H_OUT   = 256;
static constexpr int ROW4_IN  = W_IN / 4;          // 128 float4 per input row
static constexpr int ROW4_OUT = W_OUT / 4;         // 64  float4 per output row
static constexpr int IMG4_IN  = W_IN * W_IN / 4;   // 65536 float4 per input image

__device__ __forceinline__ float4 pool4(const float4& a0, const float4& a1,
                                        const float4& b0, const float4& b1,
                                        const float4& k)
{
    float4 o;
    o.x = k.x * a0.x + k.y * a0.y + k.z * b0.x + k.w * b0.y;
    o.y = k.x * a0.z + k.y * a0.w + k.z * b0.z + k.w * b0.w;
    o.z = k.x * a1.x + k.y * a1.y + k.z * b1.x + k.w * b1.y;
    o.w = k.x * a1.z + k.y * a1.w + k.z * b1.z + k.w * b1.w;
    return o;
}

__global__ __launch_bounds__(256) void Pool_26517128085982_kernel(
    const float4* __restrict__ in,
    const float*  __restrict__ kern,   // 4 floats: k00 k01 k10 k11
    float4* __restrict__ out,
    int half_n4)                       // n_out4 / 2
{
    int idx0 = blockIdx.x * blockDim.x + threadIdx.x;
    if (idx0 >= half_n4) return;
    int idx1 = idx0 + half_n4;

    // idx -> (img, oh, oc4): 64 float4 per out row, 256 rows per image
    int oc4a = idx0 & (ROW4_OUT - 1);
    int oha  = (idx0 >> 6) & (H_OUT - 1);
    int imga = idx0 >> 14;
    int basea = imga * IMG4_IN + (oha << 1) * ROW4_IN + (oc4a << 1);

    int oc4b = idx1 & (ROW4_OUT - 1);
    int ohb  = (idx1 >> 6) & (H_OUT - 1);
    int imgb = idx1 >> 14;
    int baseb = imgb * IMG4_IN + (ohb << 1) * ROW4_IN + (oc4b << 1);

    // 8 independent LDG.128 (MLP=8), front-batched, default caching
    float4 a0 = in[basea];
    float4 a1 = in[basea + 1];
    float4 b0 = in[basea + ROW4_IN];
    float4 b1 = in[basea + ROW4_IN + 1];
    float4 c0 = in[baseb];
    float4 c1 = in[baseb + 1];
    float4 d0 = in[baseb + ROW4_IN];
    float4 d1 = in[baseb + ROW4_IN + 1];

    // kernel weights: broadcast load, L1-hit after first warp
    float4 k = *reinterpret_cast<const float4*>(kern);

    out[idx0] = pool4(a0, a1, b0, b1, k);
    out[idx1] = pool4(c0, c1, d0, d1, k);
}

extern "C" void kernel_launch(void* const* d_in, const int* in_sizes, int n_in,
                              void* d_out, int out_size)
{
    const float4* x    = (const float4*)d_in[0];
    const float*  kern = (const float*)d_in[1];
    float4*       out  = (float4*)d_out;

    int n_out4  = out_size / 4;          // 16,777,216 float4
    int half_n4 = n_out4 / 2;            // 8,388,608 threads
    int blocks  = (half_n4 + 255) / 256; // 32,768 blocks
    Pool_26517128085982_kernel<<<blocks, 256>>>(x, kern, out, half_n4);
}